// round 13
// baseline (speedup 1.0000x reference)
#include <cuda_runtime.h>
#include <cuda_bf16.h>
#include <stdint.h>

// Problem constants
#define B_FEAT 128
#define U_UNITS 100000
#define K_NBR 500
#define N_RUNS 10
#define N_PAIRS 124750.0
#define T2 32             // pair tile edge
#define NTP2 136          // 16*17/2 lower-tri tile pairs (incl diagonal)
#define TILE_TASKS (NTP2 * N_RUNS)   // 1360
#define YSTRIDE 132       // float row stride: 132 mod 32 == 4 -> conflict-free frags
#define GRID_P 444        // 148 SMs x 3 persistent blocks, single wave
#define BUF_FLOATS (2 * T2 * YSTRIDE)   // Yi+Yj for one tile

// Scratch (device globals; no allocation allowed)
__device__ float  g_Y[N_RUNS][K_NBR][B_FEAT];   // normalized, tf32-rounded
__device__ float2 g_P[N_RUNS][K_NBR];           // gathered positions
__device__ double g_acc[N_RUNS][5];             // zero-init; reset by finalizer
__device__ int    g_done = 0;                   // finalize counter (reset by finalizer)

struct Choice { int v[N_RUNS]; };

// ---------------------------------------------------------------------------
// Kernel 1: gather + center + normalize + round-to-tf32 (fat grid: max MLP)
// ---------------------------------------------------------------------------
__global__ void prep_kernel(const float* __restrict__ feat,
                            const float* __restrict__ pos,
                            const int*   __restrict__ nbh,
                            Choice ch) {
    int u   = blockIdx.x;
    int run = blockIdx.y;
    int f   = threadIdx.x;
    int wid = f >> 5, lane = f & 31;

    int ind = __ldg(&nbh[ch.v[run] * K_NBR + u]);
    float v = __ldg(&feat[f * U_UNITS + ind]);

    __shared__ float ws[4];
    float s = v;
    #pragma unroll
    for (int o = 16; o > 0; o >>= 1) s += __shfl_xor_sync(0xFFFFFFFFu, s, o);
    if (lane == 0) ws[wid] = s;
    __syncthreads();
    float mean = (ws[0] + ws[1] + ws[2] + ws[3]) * (1.0f / B_FEAT);
    __syncthreads();

    float c = v - mean;
    float q = c * c;
    #pragma unroll
    for (int o = 16; o > 0; o >>= 1) q += __shfl_xor_sync(0xFFFFFFFFu, q, o);
    if (lane == 0) ws[wid] = q;
    __syncthreads();
    float inv = rsqrtf(ws[0] + ws[1] + ws[2] + ws[3]);

    float y = c * inv;
    uint32_t ytf;
    asm("cvt.rna.tf32.f32 %0, %1;" : "=r"(ytf) : "f"(y));
    g_Y[run][u][f] = __uint_as_float(ytf);
    if (f == 0) g_P[run][u] = make_float2(__ldg(&pos[ind * 2]), __ldg(&pos[ind * 2 + 1]));
}

// ---------------------------------------------------------------------------
// cp.async helpers
// ---------------------------------------------------------------------------
__device__ __forceinline__ void cpa16(uint32_t dst, const void* src, bool valid) {
    int sz = valid ? 16 : 0;
    asm volatile("cp.async.cg.shared.global [%0], [%1], 16, %2;"
                 :: "r"(dst), "l"(src), "r"(sz));
}

// ---------------------------------------------------------------------------
// Kernel 2: persistent pair kernel, cp.async double-buffered tiles.
// grid = 444 (3/SM, single wave), each block pipelines ~3 tiles:
// issue loads for tile t+1 while running MMA+epilogue on tile t.
// ---------------------------------------------------------------------------
__global__ __launch_bounds__(256) void pair_kernel(float* __restrict__ out) {
    extern __shared__ char sraw[];
    float* B0 = (float*)sraw;
    float* B1 = B0 + BUF_FLOATS;

    int tid  = threadIdx.x;
    int bid  = blockIdx.x;
    int lane = tid & 31, w = tid >> 5;
    int g4 = lane >> 2, q4 = lane & 3;
    int wy = w >> 2, wx = w & 3;

    uint32_t s0 = (uint32_t)__cvta_generic_to_shared(B0);
    uint32_t s1 = (uint32_t)__cvta_generic_to_shared(B1);

    // issue loads for tile task tt into buffer baddr
    auto issue = [&](int tt, uint32_t baddr) {
        int run = tt / NTP2;
        int t   = tt - run * NTP2;
        int ti = 0;
        while ((ti + 1) * (ti + 2) / 2 <= t) ti++;
        int tj = t - ti * (ti + 1) / 2;
        int i0 = ti * T2, j0 = tj * T2;
        #pragma unroll
        for (int it = 0; it < 8; it++) {
            int idx = tid + it * 256;               // 0..2047
            int half = idx >> 10;                   // 0: Yi rows, 1: Yj rows
            int r = (idx >> 5) & 31, c = idx & 31;
            int gr = (half ? j0 : i0) + r;
            uint32_t dst = baddr + (uint32_t)((half * T2 * YSTRIDE + r * YSTRIDE + c * 4) * 4);
            const void* src = &g_Y[run][(gr < K_NBR) ? gr : 0][c * 4];
            cpa16(dst, src, gr < K_NBR);
        }
        asm volatile("cp.async.commit_group;" ::: "memory");
    };

    // prologue
    if (bid < TILE_TASKS) issue(bid, s0);
    int parity = 0;

    for (int tt = bid; tt < TILE_TASKS; tt += GRID_P) {
        float*   cur  = parity ? B1 : B0;
        uint32_t nxtA = parity ? s0 : s1;

        asm volatile("cp.async.wait_group 0;" ::: "memory");
        __syncthreads();     // cur ready; everyone done reading the other buffer

        int ttn = tt + GRID_P;
        if (ttn < TILE_TASKS) issue(ttn, nxtA);   // overlaps with compute below

        int run = tt / NTP2;
        int t   = tt - run * NTP2;
        int ti = 0;
        while ((ti + 1) * (ti + 2) / 2 <= t) ti++;
        int tj = t - ti * (ti + 1) / 2;
        int i0 = ti * T2, j0 = tj * T2;

        const float* Arow0 = cur + (wy * 16 + g4) * YSTRIDE;
        const float* Brow  = cur + T2 * YSTRIDE + (wx * 8 + g4) * YSTRIDE;

        float acc[2][4];
        #pragma unroll
        for (int h = 0; h < 2; h++)
            #pragma unroll
            for (int e = 0; e < 4; e++) acc[h][e] = 0.f;

        #pragma unroll
        for (int ks = 0; ks < 8; ks++) {
            #pragma unroll
            for (int h = 0; h < 2; h++) {
                int k0 = (h * 8 + ks) * 8;
                uint32_t a0 = __float_as_uint(Arow0[k0 + q4]);
                uint32_t a1 = __float_as_uint(Arow0[8 * YSTRIDE + k0 + q4]);
                uint32_t a2 = __float_as_uint(Arow0[k0 + q4 + 4]);
                uint32_t a3 = __float_as_uint(Arow0[8 * YSTRIDE + k0 + q4 + 4]);
                uint32_t b0 = __float_as_uint(Brow[k0 + q4]);
                uint32_t b1 = __float_as_uint(Brow[k0 + q4 + 4]);
                asm volatile(
                    "mma.sync.aligned.m16n8k8.row.col.f32.tf32.tf32.f32 "
                    "{%0,%1,%2,%3}, {%4,%5,%6,%7}, {%8,%9}, {%0,%1,%2,%3};"
                    : "+f"(acc[h][0]), "+f"(acc[h][1]), "+f"(acc[h][2]), "+f"(acc[h][3])
                    : "r"(a0), "r"(a1), "r"(a2), "r"(a3), "r"(b0), "r"(b1));
            }
        }

        // epilogue: positions straight from L2; fast approx rsqrt/rcp
        float sr = 0.f, sd = 0.f, srd = 0.f, srr = 0.f, sdd = 0.f;
        int r0l = wy * 16 + g4;
        int c0l = wx * 8 + 2 * q4;
        #pragma unroll
        for (int e = 0; e < 4; e++) {
            int li = r0l + (e >> 1) * 8;
            int lj = c0l + (e & 1);
            int gi = i0 + li, gj = j0 + lj;
            if (gi < K_NBR && gj < K_NBR && gi > gj) {
                float2 pi = __ldg((const float2*)&g_P[run][gi]);
                float2 pj = __ldg((const float2*)&g_P[run][gj]);
                float dot = acc[0][e] + acc[1][e];
                float dx = pi.x - pj.x;
                float dy = pi.y - pj.y;
                float s2 = fmaxf(dx * dx + dy * dy, 1e-30f);
                float rs;  asm("rsqrt.approx.f32 %0, %1;" : "=f"(rs) : "f"(s2));
                float dpl = fmaf(s2, rs, 1.0f);          // d + 1
                float ds;  asm("rcp.approx.f32 %0, %1;" : "=f"(ds) : "f"(dpl));
                sr  += dot;
                sd  += ds;
                srd += dot * ds;
                srr += dot * dot;
                sdd += ds * ds;
            }
        }

        #pragma unroll
        for (int off = 16; off > 0; off >>= 1) {
            sr  += __shfl_down_sync(0xFFFFFFFFu, sr,  off);
            sd  += __shfl_down_sync(0xFFFFFFFFu, sd,  off);
            srd += __shfl_down_sync(0xFFFFFFFFu, srd, off);
            srr += __shfl_down_sync(0xFFFFFFFFu, srr, off);
            sdd += __shfl_down_sync(0xFFFFFFFFu, sdd, off);
        }
        if (lane == 0) {
            atomicAdd(&g_acc[run][0], (double)sr);
            atomicAdd(&g_acc[run][1], (double)sd);
            atomicAdd(&g_acc[run][2], (double)srd);
            atomicAdd(&g_acc[run][3], (double)srr);
            atomicAdd(&g_acc[run][4], (double)sdd);
        }
        parity ^= 1;
    }

    // ---- last-block finalize ----
    __shared__ int isLast;
    __syncthreads();
    if (tid == 0) {
        __threadfence();
        int done = atomicAdd(&g_done, 1);
        isLast = (done == GRID_P - 1) ? 1 : 0;
    }
    __syncthreads();
    if (!isLast) return;

    __shared__ double lsum[N_RUNS];
    if (tid < N_RUNS) {
        double Sr  = g_acc[tid][0], Sd  = g_acc[tid][1], Srd = g_acc[tid][2];
        double Srr = g_acc[tid][3], Sdd = g_acc[tid][4];
        double num = Srd - Sr * Sd / N_PAIRS;
        double den = sqrt((Srr - Sr * Sr / N_PAIRS) * (Sdd - Sd * Sd / N_PAIRS));
        lsum[tid] = (1.0 - num / den) * 0.5;
    }
    __syncthreads();
    if (tid == 0) {
        double s = 0;
        #pragma unroll
        for (int i = 0; i < N_RUNS; i++) s += lsum[i];
        out[0] = (float)(s / N_RUNS);
    }
    __syncthreads();
    if (tid < N_RUNS * 5) ((double*)g_acc)[tid] = 0.0;   // reset for next replay
    if (tid == 0) g_done = 0;
}

// ---------------------------------------------------------------------------
// Host-side JAX threefry2x32: choice = randint(key(42),(10,),0,100)
// ---------------------------------------------------------------------------
static inline uint32_t rotl32(uint32_t x, int r) { return (x << r) | (x >> (32 - r)); }

static void threefry2x32(uint32_t k0, uint32_t k1, uint32_t c0, uint32_t c1,
                         uint32_t* o0, uint32_t* o1) {
    uint32_t ks0 = k0, ks1 = k1, ks2 = k0 ^ k1 ^ 0x1BD11BDAu;
    uint32_t x0 = c0 + ks0, x1 = c1 + ks1;
    const int rotA[4] = {13, 15, 26, 6};
    const int rotB[4] = {17, 29, 16, 24};
#define TF_ROUND4(R) do { for (int _i = 0; _i < 4; _i++) { \
        x0 += x1; x1 = rotl32(x1, (R)[_i]); x1 ^= x0; } } while (0)
    TF_ROUND4(rotA); x0 += ks1; x1 += ks2 + 1;
    TF_ROUND4(rotB); x0 += ks2; x1 += ks0 + 2;
    TF_ROUND4(rotA); x0 += ks0; x1 += ks1 + 3;
    TF_ROUND4(rotB); x0 += ks1; x1 += ks2 + 4;
    TF_ROUND4(rotA); x0 += ks2; x1 += ks0 + 5;
#undef TF_ROUND4
    *o0 = x0; *o1 = x1;
}

extern "C" void kernel_launch(void* const* d_in, const int* in_sizes, int n_in,
                              void* d_out, int out_size) {
    const float* feat = (const float*)d_in[0];
    const float* pos  = (const float*)d_in[1];
    const int*   nbh  = (const int*)d_in[2];

    uint32_t bits[N_RUNS];
    for (uint32_t i = 0; i < 5; i++) {
        uint32_t o0, o1;
        threefry2x32(0u, 42u, i, i + 5u, &o0, &o1);
        bits[i] = o0;
        bits[i + 5] = o1;
    }
    Choice ch;
    for (int i = 0; i < N_RUNS; i++) {
        uint32_t b = bits[i];
        uint32_t hi = b >> 16, lo = b & 0xFFFFu;
        ch.v[i] = (int)(((hi % 100u) * 96u + (lo % 100u)) % 100u);
    }

    const int SMEM = 2 * BUF_FLOATS * (int)sizeof(float);   // ~67.6 KB
    cudaFuncSetAttribute(pair_kernel, cudaFuncAttributeMaxDynamicSharedMemorySize, SMEM);

    prep_kernel<<<dim3(K_NBR, N_RUNS), B_FEAT>>>(feat, pos, nbh, ch);
    pair_kernel<<<GRID_P, 256, SMEM>>>((float*)d_out);
}

// round 14
// speedup vs baseline: 2.5051x; 2.5051x over previous
#include <cuda_runtime.h>
#include <cuda_bf16.h>
#include <stdint.h>

// Problem constants
#define B_FEAT 128
#define U_UNITS 100000
#define K_NBR 500
#define N_RUNS 10
#define N_PAIRS 124750.0
#define T2 64          // pair tile edge
#define NTP2 36        // 8*9/2 lower-tri tile pairs (incl diagonal)
#define TOTAL_BLOCKS (NTP2 * N_RUNS)
#define YSTRIDE 132    // float row stride: 132 mod 32 == 4 -> conflict-free frags

// Scratch (device globals; no allocation allowed)
__device__ float  g_Y[N_RUNS][K_NBR][B_FEAT];   // normalized, tf32-rounded
__device__ float2 g_P[N_RUNS][K_NBR];           // gathered positions
__device__ double g_part[TOTAL_BLOCKS][5];      // per-block partial sums
__device__ int    g_done = 0;                   // finalize counter

struct Choice { int v[N_RUNS]; };

// ---------------------------------------------------------------------------
// Kernel 1: gather + center + normalize + round-to-tf32 (rna) feature cols
// ---------------------------------------------------------------------------
__global__ void prep_kernel(const float* __restrict__ feat,
                            const float* __restrict__ pos,
                            const int*   __restrict__ nbh,
                            Choice ch) {
    int u   = blockIdx.x;
    int run = blockIdx.y;
    int f   = threadIdx.x;
    int wid = f >> 5, lane = f & 31;

    int ind = __ldg(&nbh[ch.v[run] * K_NBR + u]);
    float v = __ldg(&feat[f * U_UNITS + ind]);

    __shared__ float ws[4];
    float s = v;
    #pragma unroll
    for (int o = 16; o > 0; o >>= 1) s += __shfl_xor_sync(0xFFFFFFFFu, s, o);
    if (lane == 0) ws[wid] = s;
    __syncthreads();
    float mean = (ws[0] + ws[1] + ws[2] + ws[3]) * (1.0f / B_FEAT);
    __syncthreads();

    float c = v - mean;
    float q = c * c;
    #pragma unroll
    for (int o = 16; o > 0; o >>= 1) q += __shfl_xor_sync(0xFFFFFFFFu, q, o);
    if (lane == 0) ws[wid] = q;
    __syncthreads();
    float inv = rsqrtf(ws[0] + ws[1] + ws[2] + ws[3]);

    float y = c * inv;
    uint32_t ytf;
    asm("cvt.rna.tf32.f32 %0, %1;" : "=r"(ytf) : "f"(y));
    g_Y[run][u][f] = __uint_as_float(ytf);
    if (f == 0) g_P[run][u] = make_float2(__ldg(&pos[ind * 2]), __ldg(&pos[ind * 2 + 1]));
}

// MUFU-free ds = 1/(1 + sqrt(s2)): bit-hack seeds + Newton (FMA/ALU pipes only)
__device__ __forceinline__ float dist_sim_nomufu(float s2) {
    // rsqrt seed + 3 Newton iterations (fp32-exact; s2==0 -> d==0)
    float y = __uint_as_float(0x5f3759dfu - (__float_as_uint(s2) >> 1));
    y = y * (1.5f - 0.5f * s2 * y * y);
    y = y * (1.5f - 0.5f * s2 * y * y);
    y = y * (1.5f - 0.5f * s2 * y * y);
    float d = s2 * y;                 // sqrt(s2)
    // reciprocal of (1+d), d+1 in [1, ~15.3]: seed + 3 Newton iterations
    float xpl = d + 1.0f;
    float r = __uint_as_float(0x7EF311C3u - __float_as_uint(xpl));
    r = r * (2.0f - xpl * r);
    r = r * (2.0f - xpl * r);
    r = r * (2.0f - xpl * r);
    return r;
}

// ---------------------------------------------------------------------------
// Kernel 2: pair sums via tf32 mma.sync.m16n8k8 (T2=64, 8 warps in 4x2 grid,
// each warp 16x32). Epilogue is MUFU-free (the former chip-wide bottleneck).
// ---------------------------------------------------------------------------
__global__ __launch_bounds__(256) void pair_kernel(float* __restrict__ out) {
    extern __shared__ char sraw[];
    float*  Ys = (float*)sraw;                   // Yi [64][132]
    float*  Yt = Ys + T2 * YSTRIDE;              // Yj [64][132]
    float2* Pi = (float2*)(Yt + T2 * YSTRIDE);
    float2* Pj = Pi + T2;

    int run = blockIdx.y;
    int t   = blockIdx.x;
    int ti = 0;
    while ((ti + 1) * (ti + 2) / 2 <= t) ti++;
    int tj = t - ti * (ti + 1) / 2;
    int i0 = ti * T2, j0 = tj * T2;

    int tid = threadIdx.x;

    for (int idx = tid; idx < T2 * 32; idx += 256) {
        int r = idx >> 5, c = idx & 31;
        int gi = i0 + r, gj = j0 + r;
        ((float4*)(Ys + r * YSTRIDE))[c] =
            (gi < K_NBR) ? ((const float4*)g_Y[run][gi])[c] : make_float4(0, 0, 0, 0);
        ((float4*)(Yt + r * YSTRIDE))[c] =
            (gj < K_NBR) ? ((const float4*)g_Y[run][gj])[c] : make_float4(0, 0, 0, 0);
    }
    if (tid < T2) {
        Pi[tid] = (i0 + tid < K_NBR) ? g_P[run][i0 + tid] : make_float2(0, 0);
    } else if (tid < 2 * T2) {
        int k = tid - T2;
        Pj[k] = (j0 + k < K_NBR) ? g_P[run][j0 + k] : make_float2(0, 0);
    }
    __syncthreads();

    int lane = tid & 31, w = tid >> 5;
    int wy = w >> 1, wx = w & 1;
    int g4 = lane >> 2, q4 = lane & 3;

    const float* Arow0 = Ys + (wy * 16 + g4) * YSTRIDE;
    const float* Bbase = Yt + (wx * 32 + g4) * YSTRIDE;

    float acc[4][4];
    #pragma unroll
    for (int nt = 0; nt < 4; nt++)
        #pragma unroll
        for (int e = 0; e < 4; e++) acc[nt][e] = 0.f;

    #pragma unroll 4
    for (int ks = 0; ks < 16; ks++) {
        int k0 = ks * 8;
        uint32_t a0 = __float_as_uint(Arow0[k0 + q4]);
        uint32_t a1 = __float_as_uint(Arow0[8 * YSTRIDE + k0 + q4]);
        uint32_t a2 = __float_as_uint(Arow0[k0 + q4 + 4]);
        uint32_t a3 = __float_as_uint(Arow0[8 * YSTRIDE + k0 + q4 + 4]);
        #pragma unroll
        for (int nt = 0; nt < 4; nt++) {
            uint32_t b0 = __float_as_uint(Bbase[nt * 8 * YSTRIDE + k0 + q4]);
            uint32_t b1 = __float_as_uint(Bbase[nt * 8 * YSTRIDE + k0 + q4 + 4]);
            asm volatile(
                "mma.sync.aligned.m16n8k8.row.col.f32.tf32.tf32.f32 "
                "{%0,%1,%2,%3}, {%4,%5,%6,%7}, {%8,%9}, {%0,%1,%2,%3};"
                : "+f"(acc[nt][0]), "+f"(acc[nt][1]), "+f"(acc[nt][2]), "+f"(acc[nt][3])
                : "r"(a0), "r"(a1), "r"(a2), "r"(a3), "r"(b0), "r"(b1));
        }
    }

    // epilogue: thread owns D rows {wy*16+g4, +8}, cols {wx*32+nt*8+2*q4, +1}
    float sr = 0.f, sd = 0.f, srd = 0.f, srr = 0.f, sdd = 0.f;
    int r0l = wy * 16 + g4;
    #pragma unroll
    for (int nt = 0; nt < 4; nt++) {
        int c0l = wx * 32 + nt * 8 + 2 * q4;
        #pragma unroll
        for (int e = 0; e < 4; e++) {
            int li = r0l + (e >> 1) * 8;
            int lj = c0l + (e & 1);
            int gi = i0 + li, gj = j0 + lj;
            if (gi < K_NBR && gj < K_NBR && gi > gj) {
                float dot = acc[nt][e];
                float dx = Pi[li].x - Pj[lj].x;
                float dy = Pi[li].y - Pj[lj].y;
                float ds = dist_sim_nomufu(dx * dx + dy * dy);
                sr  += dot;
                sd  += ds;
                srd += dot * ds;
                srr += dot * dot;
                sdd += ds * ds;
            }
        }
    }

    // block reduce 5 sums
    #pragma unroll
    for (int off = 16; off > 0; off >>= 1) {
        sr  += __shfl_down_sync(0xFFFFFFFFu, sr,  off);
        sd  += __shfl_down_sync(0xFFFFFFFFu, sd,  off);
        srd += __shfl_down_sync(0xFFFFFFFFu, srd, off);
        srr += __shfl_down_sync(0xFFFFFFFFu, srr, off);
        sdd += __shfl_down_sync(0xFFFFFFFFu, sdd, off);
    }
    __shared__ float wsum[8][5];
    if (lane == 0) {
        wsum[w][0] = sr;  wsum[w][1] = sd;  wsum[w][2] = srd;
        wsum[w][3] = srr; wsum[w][4] = sdd;
    }
    __syncthreads();
    if (tid == 0) {
        double a0 = 0, a1 = 0, a2 = 0, a3 = 0, a4 = 0;
        #pragma unroll
        for (int ww = 0; ww < 8; ww++) {
            a0 += wsum[ww][0]; a1 += wsum[ww][1]; a2 += wsum[ww][2];
            a3 += wsum[ww][3]; a4 += wsum[ww][4];
        }
        double* p = g_part[run * NTP2 + t];
        p[0] = a0; p[1] = a1; p[2] = a2; p[3] = a3; p[4] = a4;
    }

    // ---- last-block finalize ----
    __shared__ int isLast;
    if (tid == 0) {
        __threadfence();
        int done = atomicAdd(&g_done, 1);
        isLast = (done == TOTAL_BLOCKS - 1) ? 1 : 0;
    }
    __syncthreads();
    if (!isLast) return;

    __shared__ double red[50];
    if (tid < 50) {
        int rn = tid / 5, cp = tid % 5;
        double s = 0;
        for (int b2 = 0; b2 < NTP2; b2++) s += g_part[rn * NTP2 + b2][cp];
        red[tid] = s;
    }
    __syncthreads();
    __shared__ double lsum[N_RUNS];
    if (tid < N_RUNS) {
        double Sr  = red[tid * 5 + 0], Sd  = red[tid * 5 + 1], Srd = red[tid * 5 + 2];
        double Srr = red[tid * 5 + 3], Sdd = red[tid * 5 + 4];
        double num = Srd - Sr * Sd / N_PAIRS;
        double den = sqrt((Srr - Sr * Sr / N_PAIRS) * (Sdd - Sd * Sd / N_PAIRS));
        lsum[tid] = (1.0 - num / den) * 0.5;
    }
    __syncthreads();
    if (tid == 0) {
        double s = 0;
        #pragma unroll
        for (int i = 0; i < N_RUNS; i++) s += lsum[i];
        out[0] = (float)(s / N_RUNS);
        g_done = 0;  // reset for next graph replay
    }
}

// ---------------------------------------------------------------------------
// Host-side JAX threefry2x32: choice = randint(key(42),(10,),0,100)
// ---------------------------------------------------------------------------
static inline uint32_t rotl32(uint32_t x, int r) { return (x << r) | (x >> (32 - r)); }

static void threefry2x32(uint32_t k0, uint32_t k1, uint32_t c0, uint32_t c1,
                         uint32_t* o0, uint32_t* o1) {
    uint32_t ks0 = k0, ks1 = k1, ks2 = k0 ^ k1 ^ 0x1BD11BDAu;
    uint32_t x0 = c0 + ks0, x1 = c1 + ks1;
    const int rotA[4] = {13, 15, 26, 6};
    const int rotB[4] = {17, 29, 16, 24};
#define TF_ROUND4(R) do { for (int _i = 0; _i < 4; _i++) { \
        x0 += x1; x1 = rotl32(x1, (R)[_i]); x1 ^= x0; } } while (0)
    TF_ROUND4(rotA); x0 += ks1; x1 += ks2 + 1;
    TF_ROUND4(rotB); x0 += ks2; x1 += ks0 + 2;
    TF_ROUND4(rotA); x0 += ks0; x1 += ks1 + 3;
    TF_ROUND4(rotB); x0 += ks1; x1 += ks2 + 4;
    TF_ROUND4(rotA); x0 += ks2; x1 += ks0 + 5;
#undef TF_ROUND4
    *o0 = x0; *o1 = x1;
}

extern "C" void kernel_launch(void* const* d_in, const int* in_sizes, int n_in,
                              void* d_out, int out_size) {
    const float* feat = (const float*)d_in[0];
    const float* pos  = (const float*)d_in[1];
    const int*   nbh  = (const int*)d_in[2];

    uint32_t bits[N_RUNS];
    for (uint32_t i = 0; i < 5; i++) {
        uint32_t o0, o1;
        threefry2x32(0u, 42u, i, i + 5u, &o0, &o1);
        bits[i] = o0;
        bits[i + 5] = o1;
    }
    Choice ch;
    for (int i = 0; i < N_RUNS; i++) {
        uint32_t b = bits[i];
        uint32_t hi = b >> 16, lo = b & 0xFFFFu;
        ch.v[i] = (int)(((hi % 100u) * 96u + (lo % 100u)) % 100u);
    }

    const int SMEM = 2 * T2 * YSTRIDE * (int)sizeof(float) + 2 * T2 * (int)sizeof(float2);
    cudaFuncSetAttribute(pair_kernel, cudaFuncAttributeMaxDynamicSharedMemorySize, SMEM);

    prep_kernel<<<dim3(K_NBR, N_RUNS), B_FEAT>>>(feat, pos, nbh, ch);
    pair_kernel<<<dim3(NTP2, N_RUNS), 256, SMEM>>>((float*)d_out);
}

// round 15
// speedup vs baseline: 2.5637x; 1.0234x over previous
#include <cuda_runtime.h>
#include <cuda_bf16.h>
#include <stdint.h>

// Problem constants
#define B_FEAT 128
#define U_UNITS 100000
#define K_NBR 500
#define N_RUNS 10
#define N_PAIRS 124750.0
#define T2 64          // pair tile edge
#define NTP2 36        // 8*9/2 lower-tri tile pairs (incl diagonal)
#define TOTAL_BLOCKS (NTP2 * N_RUNS)
#define YSTRIDE 132    // float row stride: 132 mod 32 == 4 -> conflict-free frags

// Scratch (device globals; no allocation allowed)
__device__ float  g_Y[N_RUNS][K_NBR][B_FEAT];   // normalized, tf32-rounded
__device__ float2 g_P[N_RUNS][K_NBR];           // gathered positions
__device__ double g_part[TOTAL_BLOCKS][5];      // per-block partial sums
__device__ int    g_done = 0;                   // finalize counter

struct Choice { int v[N_RUNS]; };

// ---------------------------------------------------------------------------
// Kernel 1: gather + center + normalize + round-to-tf32 (rna) feature cols
// ---------------------------------------------------------------------------
__global__ void prep_kernel(const float* __restrict__ feat,
                            const float* __restrict__ pos,
                            const int*   __restrict__ nbh,
                            Choice ch) {
    int u   = blockIdx.x;
    int run = blockIdx.y;
    int f   = threadIdx.x;
    int wid = f >> 5, lane = f & 31;

    int ind = __ldg(&nbh[ch.v[run] * K_NBR + u]);
    float v = __ldg(&feat[f * U_UNITS + ind]);

    __shared__ float ws[4];
    float s = v;
    #pragma unroll
    for (int o = 16; o > 0; o >>= 1) s += __shfl_xor_sync(0xFFFFFFFFu, s, o);
    if (lane == 0) ws[wid] = s;
    __syncthreads();
    float mean = (ws[0] + ws[1] + ws[2] + ws[3]) * (1.0f / B_FEAT);
    __syncthreads();

    float c = v - mean;
    float q = c * c;
    #pragma unroll
    for (int o = 16; o > 0; o >>= 1) q += __shfl_xor_sync(0xFFFFFFFFu, q, o);
    if (lane == 0) ws[wid] = q;
    __syncthreads();
    float inv = rsqrtf(ws[0] + ws[1] + ws[2] + ws[3]);

    float y = c * inv;
    uint32_t ytf;
    asm("cvt.rna.tf32.f32 %0, %1;" : "=r"(ytf) : "f"(y));
    g_Y[run][u][f] = __uint_as_float(ytf);
    if (f == 0) g_P[run][u] = make_float2(__ldg(&pos[ind * 2]), __ldg(&pos[ind * 2 + 1]));
}

// MUFU-free ds = 1/(1 + sqrt(s2)); 2+2 Newton, ~7e-6 rel err, FMA/ALU only.
// Safe at s2 == 0: (h*y)*y keeps the zero before any overflow can form.
__device__ __forceinline__ float dist_sim_nomufu(float s2) {
    float h = 0.5f * s2;
    float y = __uint_as_float(0x5f3759dfu - (__float_as_uint(s2) >> 1));
    float t0 = h * y;  y = y * fmaf(-t0, y, 1.5f);
    float t1 = h * y;  y = y * fmaf(-t1, y, 1.5f);
    float d = s2 * y;                     // sqrt(s2)
    float xpl = d + 1.0f;                 // in [1, ~15.3]
    float r = __uint_as_float(0x7EF311C3u - __float_as_uint(xpl));
    r = r * fmaf(-xpl, r, 2.0f);
    r = r * fmaf(-xpl, r, 2.0f);
    return r;
}

// ---------------------------------------------------------------------------
// Kernel 2: pair sums via tf32 mma.sync.m16n8k8 (T2=64, 8 warps in 4x2 grid,
// each warp 16x32). Branchless masked epilogue, MUFU-free.
// ---------------------------------------------------------------------------
__global__ __launch_bounds__(256) void pair_kernel(float* __restrict__ out) {
    extern __shared__ char sraw[];
    float*  Ys = (float*)sraw;                   // Yi [64][132]
    float*  Yt = Ys + T2 * YSTRIDE;              // Yj [64][132]
    float2* Pi = (float2*)(Yt + T2 * YSTRIDE);
    float2* Pj = Pi + T2;

    int run = blockIdx.y;
    int t   = blockIdx.x;
    int ti = 0;
    while ((ti + 1) * (ti + 2) / 2 <= t) ti++;
    int tj = t - ti * (ti + 1) / 2;
    int i0 = ti * T2, j0 = tj * T2;

    int tid = threadIdx.x;

    for (int idx = tid; idx < T2 * 32; idx += 256) {
        int r = idx >> 5, c = idx & 31;
        int gi = i0 + r, gj = j0 + r;
        ((float4*)(Ys + r * YSTRIDE))[c] =
            (gi < K_NBR) ? ((const float4*)g_Y[run][gi])[c] : make_float4(0, 0, 0, 0);
        ((float4*)(Yt + r * YSTRIDE))[c] =
            (gj < K_NBR) ? ((const float4*)g_Y[run][gj])[c] : make_float4(0, 0, 0, 0);
    }
    if (tid < T2) {
        Pi[tid] = (i0 + tid < K_NBR) ? g_P[run][i0 + tid] : make_float2(0, 0);
    } else if (tid < 2 * T2) {
        int k = tid - T2;
        Pj[k] = (j0 + k < K_NBR) ? g_P[run][j0 + k] : make_float2(0, 0);
    }
    __syncthreads();

    int lane = tid & 31, w = tid >> 5;
    int wy = w >> 1, wx = w & 1;
    int g4 = lane >> 2, q4 = lane & 3;

    const float* Arow0 = Ys + (wy * 16 + g4) * YSTRIDE;
    const float* Bbase = Yt + (wx * 32 + g4) * YSTRIDE;

    float acc[4][4];
    #pragma unroll
    for (int nt = 0; nt < 4; nt++)
        #pragma unroll
        for (int e = 0; e < 4; e++) acc[nt][e] = 0.f;

    #pragma unroll
    for (int ks = 0; ks < 16; ks++) {
        int k0 = ks * 8;
        uint32_t a0 = __float_as_uint(Arow0[k0 + q4]);
        uint32_t a1 = __float_as_uint(Arow0[8 * YSTRIDE + k0 + q4]);
        uint32_t a2 = __float_as_uint(Arow0[k0 + q4 + 4]);
        uint32_t a3 = __float_as_uint(Arow0[8 * YSTRIDE + k0 + q4 + 4]);
        #pragma unroll
        for (int nt = 0; nt < 4; nt++) {
            uint32_t b0 = __float_as_uint(Bbase[nt * 8 * YSTRIDE + k0 + q4]);
            uint32_t b1 = __float_as_uint(Bbase[nt * 8 * YSTRIDE + k0 + q4 + 4]);
            asm volatile(
                "mma.sync.aligned.m16n8k8.row.col.f32.tf32.tf32.f32 "
                "{%0,%1,%2,%3}, {%4,%5,%6,%7}, {%8,%9}, {%0,%1,%2,%3};"
                : "+f"(acc[nt][0]), "+f"(acc[nt][1]), "+f"(acc[nt][2]), "+f"(acc[nt][3])
                : "r"(a0), "r"(a1), "r"(a2), "r"(a3), "r"(b0), "r"(b1));
        }
    }

    // branchless masked epilogue:
    // thread owns D rows {wy*16+g4, +8}, cols {wx*32+nt*8+2*q4, +1}
    float sr = 0.f, sd = 0.f, srd = 0.f, srr = 0.f, sdd = 0.f;
    int r0l = wy * 16 + g4;
    #pragma unroll
    for (int nt = 0; nt < 4; nt++) {
        int c0l = wx * 32 + nt * 8 + 2 * q4;
        #pragma unroll
        for (int e = 0; e < 4; e++) {
            int li = r0l + (e >> 1) * 8;
            int lj = c0l + (e & 1);
            int gi = i0 + li, gj = j0 + lj;
            float m = (gi < K_NBR && gj < K_NBR && gi > gj) ? 1.0f : 0.0f;
            float dot = acc[nt][e];
            float dx = Pi[li].x - Pj[lj].x;
            float dy = Pi[li].y - Pj[lj].y;
            float s2 = fmaf(dy, dy, dx * dx);
            float ds = dist_sim_nomufu(s2);
            float dm = m * dot;
            float rm = m * ds;
            sr  += dm;
            sd  += rm;
            srd = fmaf(dm, ds, srd);
            srr = fmaf(dm, dot, srr);
            sdd = fmaf(rm, ds, sdd);
        }
    }

    // block reduce 5 sums
    #pragma unroll
    for (int off = 16; off > 0; off >>= 1) {
        sr  += __shfl_down_sync(0xFFFFFFFFu, sr,  off);
        sd  += __shfl_down_sync(0xFFFFFFFFu, sd,  off);
        srd += __shfl_down_sync(0xFFFFFFFFu, srd, off);
        srr += __shfl_down_sync(0xFFFFFFFFu, srr, off);
        sdd += __shfl_down_sync(0xFFFFFFFFu, sdd, off);
    }
    __shared__ float wsum[8][5];
    if (lane == 0) {
        wsum[w][0] = sr;  wsum[w][1] = sd;  wsum[w][2] = srd;
        wsum[w][3] = srr; wsum[w][4] = sdd;
    }
    __syncthreads();
    if (tid == 0) {
        double a0 = 0, a1 = 0, a2 = 0, a3 = 0, a4 = 0;
        #pragma unroll
        for (int ww = 0; ww < 8; ww++) {
            a0 += wsum[ww][0]; a1 += wsum[ww][1]; a2 += wsum[ww][2];
            a3 += wsum[ww][3]; a4 += wsum[ww][4];
        }
        double* p = g_part[run * NTP2 + t];
        p[0] = a0; p[1] = a1; p[2] = a2; p[3] = a3; p[4] = a4;
    }

    // ---- last-block finalize ----
    __shared__ int isLast;
    if (tid == 0) {
        __threadfence();
        int done = atomicAdd(&g_done, 1);
        isLast = (done == TOTAL_BLOCKS - 1) ? 1 : 0;
    }
    __syncthreads();
    if (!isLast) return;

    __shared__ double red[50];
    if (tid < 50) {
        int rn = tid / 5, cp = tid % 5;
        double s = 0;
        for (int b2 = 0; b2 < NTP2; b2++) s += g_part[rn * NTP2 + b2][cp];
        red[tid] = s;
    }
    __syncthreads();
    __shared__ double lsum[N_RUNS];
    if (tid < N_RUNS) {
        double Sr  = red[tid * 5 + 0], Sd  = red[tid * 5 + 1], Srd = red[tid * 5 + 2];
        double Srr = red[tid * 5 + 3], Sdd = red[tid * 5 + 4];
        double num = Srd - Sr * Sd / N_PAIRS;
        double den = sqrt((Srr - Sr * Sr / N_PAIRS) * (Sdd - Sd * Sd / N_PAIRS));
        lsum[tid] = (1.0 - num / den) * 0.5;
    }
    __syncthreads();
    if (tid == 0) {
        double s = 0;
        #pragma unroll
        for (int i = 0; i < N_RUNS; i++) s += lsum[i];
        out[0] = (float)(s / N_RUNS);
        g_done = 0;  // reset for next graph replay
    }
}

// ---------------------------------------------------------------------------
// Host-side JAX threefry2x32: choice = randint(key(42),(10,),0,100)
// ---------------------------------------------------------------------------
static inline uint32_t rotl32(uint32_t x, int r) { return (x << r) | (x >> (32 - r)); }

static void threefry2x32(uint32_t k0, uint32_t k1, uint32_t c0, uint32_t c1,
                         uint32_t* o0, uint32_t* o1) {
    uint32_t ks0 = k0, ks1 = k1, ks2 = k0 ^ k1 ^ 0x1BD11BDAu;
    uint32_t x0 = c0 + ks0, x1 = c1 + ks1;
    const int rotA[4] = {13, 15, 26, 6};
    const int rotB[4] = {17, 29, 16, 24};
#define TF_ROUND4(R) do { for (int _i = 0; _i < 4; _i++) { \
        x0 += x1; x1 = rotl32(x1, (R)[_i]); x1 ^= x0; } } while (0)
    TF_ROUND4(rotA); x0 += ks1; x1 += ks2 + 1;
    TF_ROUND4(rotB); x0 += ks2; x1 += ks0 + 2;
    TF_ROUND4(rotA); x0 += ks0; x1 += ks1 + 3;
    TF_ROUND4(rotB); x0 += ks1; x1 += ks2 + 4;
    TF_ROUND4(rotA); x0 += ks2; x1 += ks0 + 5;
#undef TF_ROUND4
    *o0 = x0; *o1 = x1;
}

extern "C" void kernel_launch(void* const* d_in, const int* in_sizes, int n_in,
                              void* d_out, int out_size) {
    const float* feat = (const float*)d_in[0];
    const float* pos  = (const float*)d_in[1];
    const int*   nbh  = (const int*)d_in[2];

    uint32_t bits[N_RUNS];
    for (uint32_t i = 0; i < 5; i++) {
        uint32_t o0, o1;
        threefry2x32(0u, 42u, i, i + 5u, &o0, &o1);
        bits[i] = o0;
        bits[i + 5] = o1;
    }
    Choice ch;
    for (int i = 0; i < N_RUNS; i++) {
        uint32_t b = bits[i];
        uint32_t hi = b >> 16, lo = b & 0xFFFFu;
        ch.v[i] = (int)(((hi % 100u) * 96u + (lo % 100u)) % 100u);
    }

    const int SMEM = 2 * T2 * YSTRIDE * (int)sizeof(float) + 2 * T2 * (int)sizeof(float2);
    cudaFuncSetAttribute(pair_kernel, cudaFuncAttributeMaxDynamicSharedMemorySize, SMEM);

    prep_kernel<<<dim3(K_NBR, N_RUNS), B_FEAT>>>(feat, pos, nbh, ch);
    pair_kernel<<<dim3(NTP2, N_RUNS), 256, SMEM>>>((float*)d_out);
}